// round 8
// baseline (speedup 1.0000x reference)
#include <cuda_runtime.h>
#include <cuda_bf16.h>
#include <math.h>
#include <cstdint>

#define BATCH 16
#define NPTS  2048
#define DIM   128
#define TILE  128
#define NJT   (NPTS / TILE)            // 16
#define NPAIRS (NJT * (NJT + 1) / 2)   // 136
#define NITEMS (NPAIRS * BATCH)        // 2176
#define NSM   152                      // GB300: 152 SMs

// ---------------- scratch (no runtime allocation allowed) -------------------
__device__ float         g_sqnorms[BATCH * NPTS];
__device__ unsigned int  g_minsq[BATCH * NPTS];      // fp32 bits, atomicMin
__device__ __nv_bfloat16 g_hi[BATCH * NPTS * DIM];   // 8 MB

// ---------------- smem: A 32K | B0 32K | B1 32K | red 3K --------------------
#define SM_A     0u
#define SM_B(s)  (32768u + (uint32_t)(s) * 32768u)
#define SM_RED   98304
#define SMEM_TOTAL (98304 + 3072)

__device__ __forceinline__ uint32_t swz(uint32_t off) {
    return off ^ ((off >> 4) & 0x70);
}
__device__ __forceinline__ uint32_t smem_u32(const void* p) {
    uint32_t a;
    asm("{ .reg .u64 t; cvta.to.shared.u64 t, %1; cvt.u32.u64 %0, t; }"
        : "=r"(a) : "l"(p));
    return a;
}
__device__ __forceinline__ void cp16(uint32_t dst, const void* src) {
    asm volatile("cp.async.ca.shared.global [%0], [%1], 16;" :: "r"(dst), "l"(src));
}
#define CP_COMMIT() asm volatile("cp.async.commit_group;" ::: "memory")

__device__ __forceinline__ void ldsm_x4(unsigned* r, uint32_t addr) {
    asm volatile("ldmatrix.sync.aligned.m8n8.x4.shared.b16 {%0,%1,%2,%3}, [%4];"
        : "=r"(r[0]), "=r"(r[1]), "=r"(r[2]), "=r"(r[3]) : "r"(addr));
}
__device__ __forceinline__ void ldsm_x2(unsigned* r, uint32_t addr) {
    asm volatile("ldmatrix.sync.aligned.m8n8.x2.shared.b16 {%0,%1}, [%2];"
        : "=r"(r[0]), "=r"(r[1]) : "r"(addr));
}
__device__ __forceinline__ void mma16816(float* d, const unsigned* a, const unsigned* b) {
    asm volatile(
        "mma.sync.aligned.m16n8k16.row.col.f32.bf16.bf16.f32 "
        "{%0,%1,%2,%3}, {%4,%5,%6,%7}, {%8,%9}, {%0,%1,%2,%3};"
        : "+f"(d[0]), "+f"(d[1]), "+f"(d[2]), "+f"(d[3])
        : "r"(a[0]), "r"(a[1]), "r"(a[2]), "r"(a[3]), "r"(b[0]), "r"(b[1]));
}

__device__ __forceinline__ void decode_item(int item, int& b, int& it, int& jt) {
    b = item / NPAIRS;
    int rem = item - b * NPAIRS;
    int i = 0;
    while (rem >= NJT - i) { rem -= NJT - i; i++; }
    it = i; jt = i + rem;
}

// cp.async a 128x128 bf16 tile into swizzled 256B-row smem
__device__ __forceinline__ void cp_tile(uint32_t smem_u, uint32_t off,
                                        const __nv_bfloat16* g, int row0, int tid) {
    const uint4* src = (const uint4*)(g + (size_t)row0 * DIM);
    #pragma unroll
    for (int it = 0; it < 8; it++) {
        int idx = tid + 256 * it;
        cp16(smem_u + off + swz((uint32_t)idx * 16u), src + idx);
    }
}

// ---------------------------------------------------------------------------
// Kernel 1: per-row sqnorm + bf16 hi plane + minsq init (warp loops 8 rows)
// ---------------------------------------------------------------------------
__global__ void prep_kernel(const float* __restrict__ x) {
    int warp_id = (blockIdx.x * blockDim.x + threadIdx.x) >> 5;
    int lane    = threadIdx.x & 31;
    int row0    = warp_id * 8;
    if (row0 >= BATCH * NPTS) return;
    #pragma unroll
    for (int r = 0; r < 8; r++) {
        int row = row0 + r;
        float4 v = ((const float4*)(x + (size_t)row * DIM))[lane];
        float s = v.x * v.x + v.y * v.y + v.z * v.z + v.w * v.w;
        #pragma unroll
        for (int o = 16; o; o >>= 1) s += __shfl_xor_sync(0xffffffffu, s, o);

        __nv_bfloat162* ph = (__nv_bfloat162*)g_hi;
        int base = row * 64 + lane * 2;
        ph[base]     = __halves2bfloat162(__float2bfloat16(v.x), __float2bfloat16(v.y));
        ph[base + 1] = __halves2bfloat162(__float2bfloat16(v.z), __float2bfloat16(v.w));
        if (lane == 0) {
            g_sqnorms[row] = s;
            g_minsq[row]   = 0x7F800000u;   // +inf
        }
    }
}

// ---------------------------------------------------------------------------
// Kernel 2: persistent CTAs over CONTIGUOUS item chunks. A-resident,
// B double-buffered one item ahead. occ 2 hides epilogue under peer MMA.
// Group discipline: wait_group 1 leaves exactly the newest B prefetch
// pending; boundary A-loads are older groups and thus complete.
// ---------------------------------------------------------------------------
__global__ __launch_bounds__(256, 2)
void nnd_persist_kernel() {
    extern __shared__ char smem[];
    const int tid  = threadIdx.x;
    const int lane = tid & 31;
    const int wid  = tid >> 5;
    const int wm   = wid >> 2;
    const int wn   = wid & 3;
    const uint32_t smem_u = smem_u32(smem);

    const int r8  = lane & 7;
    const int q   = lane >> 3;
    const int l15 = lane & 15;
    const int rb  = l15 & 7;
    const int hb  = l15 >> 3;
    const int g   = lane >> 2;
    const int t   = lane & 3;

    float* red_row = (float*)(smem + SM_RED);          // [128][4]
    float* red_col = (float*)(smem + SM_RED + 2048);   // [128][2]

    const uint32_t a_row = (uint32_t)(wm * 64 + ((q & 1) << 3) + r8);
    const uint32_t a_kq  = (uint32_t)((q >> 1) << 4);
    const uint32_t b_row = (uint32_t)(wn * 32 + rb);
    const uint32_t b_kq  = (uint32_t)(hb << 4);

    // contiguous chunk [n0, n1)
    const int n0 = (int)((long long)blockIdx.x * NITEMS / NSM);
    const int n1 = (int)((long long)(blockIdx.x + 1) * NITEMS / NSM);
    const int len = n1 - n0;

    int cb, cit, cjt;                       // current item decode
    decode_item(n0, cb, cit, cjt);

    // prologue: A + B(stage0) for first item, one group
    {
        const __nv_bfloat16* Hb = g_hi + (size_t)cb * NPTS * DIM;
        cp_tile(smem_u, SM_A, Hb, cit * TILE, tid);
        if (cjt != cit) cp_tile(smem_u, SM_B(0), Hb, cjt * TILE, tid);
        CP_COMMIT();
    }

    int nb = cb, nit = cit, njt = cjt;      // next item decode (carried)

    for (int l = 0; l < len; l++) {
        const int s = l & 1;
        const int b = cb, it = cit, jt = cjt;
        const bool diag = (it == jt);

        // prefetch NEXT item's B into the other stage
        bool have_next = (l + 1 < len);
        bool a_changes = false;
        if (have_next) {
            decode_item(n0 + l + 1, nb, nit, njt);
            a_changes = (nb != b) || (nit != it);
            const __nv_bfloat16* Hn = g_hi + (size_t)nb * NPTS * DIM;
            if (njt != nit) cp_tile(smem_u, SM_B(s ^ 1), Hn, njt * TILE, tid);
        }
        CP_COMMIT();                        // always commit (possibly empty)

        asm volatile("cp.async.wait_group 1;" ::: "memory");
        __syncthreads();

        const int i0 = it * TILE, j0 = jt * TILE;
        const float* qsg = g_sqnorms + b * NPTS;
        const uint32_t sa = smem_u + SM_A;
        const uint32_t sb = diag ? sa : (smem_u + SM_B(s));

        float d[4][4][4];
        #pragma unroll
        for (int mt = 0; mt < 4; mt++)
            #pragma unroll
            for (int nt = 0; nt < 4; nt++)
                #pragma unroll
                for (int e = 0; e < 4; e++) d[mt][nt][e] = 0.0f;

        #pragma unroll
        for (int ks = 0; ks < 8; ks++) {
            const uint32_t kb = (uint32_t)ks * 32u;
            unsigned ah[4][4], bf[4][2];
            #pragma unroll
            for (int mt = 0; mt < 4; mt++)
                ldsm_x4(ah[mt], sa + swz((a_row + (uint32_t)(mt * 16)) * 256u + kb + a_kq));
            #pragma unroll
            for (int nt = 0; nt < 4; nt++)
                ldsm_x2(bf[nt], sb + swz((b_row + (uint32_t)(nt * 8)) * 256u + kb + b_kq));
            #pragma unroll
            for (int mt = 0; mt < 4; mt++)
                #pragma unroll
                for (int nt = 0; nt < 4; nt++)
                    mma16816(d[mt][nt], ah[mt], bf[nt]);
        }

        // ---- epilogue: row-side mins ----
        float rmin[8];
        #pragma unroll
        for (int r = 0; r < 8; r++) rmin[r] = 3.4e38f;
        #pragma unroll
        for (int nt = 0; nt < 4; nt++) {
            const int gc0 = j0 + wn * 32 + nt * 8 + 2 * t;
            const float qjx = qsg[gc0], qjy = qsg[gc0 + 1];
            #pragma unroll
            for (int mt = 0; mt < 4; mt++) {
                const int gr0 = i0 + wm * 64 + mt * 16 + g;
                const int gr1 = gr0 + 8;
                float c00 = fmaf(-2.0f, d[mt][nt][0], qjx);
                float c01 = fmaf(-2.0f, d[mt][nt][1], qjy);
                float c10 = fmaf(-2.0f, d[mt][nt][2], qjx);
                float c11 = fmaf(-2.0f, d[mt][nt][3], qjy);
                if (!diag || gr0 != gc0)     rmin[2*mt]   = fminf(rmin[2*mt],   c00);
                if (!diag || gr0 != gc0 + 1) rmin[2*mt]   = fminf(rmin[2*mt],   c01);
                if (!diag || gr1 != gc0)     rmin[2*mt+1] = fminf(rmin[2*mt+1], c10);
                if (!diag || gr1 != gc0 + 1) rmin[2*mt+1] = fminf(rmin[2*mt+1], c11);
            }
        }
        #pragma unroll
        for (int r = 0; r < 8; r++) {
            rmin[r] = fminf(rmin[r], __shfl_xor_sync(0xffffffffu, rmin[r], 1));
            rmin[r] = fminf(rmin[r], __shfl_xor_sync(0xffffffffu, rmin[r], 2));
        }
        __syncthreads();                    // all warps done with A smem

        // boundary: issue next A load now (overlaps epilogue below)
        if (have_next && a_changes) {
            cp_tile(smem_u, SM_A, g_hi + (size_t)nb * NPTS * DIM, nit * TILE, tid);
            CP_COMMIT();
        }

        if (t == 0) {
            #pragma unroll
            for (int mt = 0; mt < 4; mt++) {
                int rl = wm * 64 + mt * 16 + g;
                red_row[rl * 4 + wn]       = rmin[2 * mt];
                red_row[(rl + 8) * 4 + wn] = rmin[2 * mt + 1];
            }
        }

        // ---- col-side mins (off-diagonal tiles only) ----
        if (!diag) {
            float cmin[4][2];
            #pragma unroll
            for (int nt = 0; nt < 4; nt++) { cmin[nt][0] = 3.4e38f; cmin[nt][1] = 3.4e38f; }
            #pragma unroll
            for (int mt = 0; mt < 4; mt++) {
                const int gr0 = i0 + wm * 64 + mt * 16 + g;
                const float qi0 = qsg[gr0], qi1 = qsg[gr0 + 8];
                #pragma unroll
                for (int nt = 0; nt < 4; nt++) {
                    cmin[nt][0] = fminf(cmin[nt][0], fmaf(-2.0f, d[mt][nt][0], qi0));
                    cmin[nt][1] = fminf(cmin[nt][1], fmaf(-2.0f, d[mt][nt][1], qi0));
                    cmin[nt][0] = fminf(cmin[nt][0], fmaf(-2.0f, d[mt][nt][2], qi1));
                    cmin[nt][1] = fminf(cmin[nt][1], fmaf(-2.0f, d[mt][nt][3], qi1));
                }
            }
            #pragma unroll
            for (int nt = 0; nt < 4; nt++)
                #pragma unroll
                for (int e = 0; e < 2; e++) {
                    float v = cmin[nt][e];
                    v = fminf(v, __shfl_xor_sync(0xffffffffu, v, 4));
                    v = fminf(v, __shfl_xor_sync(0xffffffffu, v, 8));
                    v = fminf(v, __shfl_xor_sync(0xffffffffu, v, 16));
                    cmin[nt][e] = v;
                }
            if (lane < 4) {
                #pragma unroll
                for (int nt = 0; nt < 4; nt++) {
                    int c0 = wn * 32 + nt * 8 + 2 * lane;
                    red_col[c0 * 2 + wm]       = cmin[nt][0];
                    red_col[(c0 + 1) * 2 + wm] = cmin[nt][1];
                }
            }
        }
        __syncthreads();

        if (tid < 128) {
            float m = fminf(fminf(red_row[tid * 4 + 0], red_row[tid * 4 + 1]),
                            fminf(red_row[tid * 4 + 2], red_row[tid * 4 + 3]));
            float cand = fmaxf(qsg[i0 + tid] + m, 0.0f);
            atomicMin(&g_minsq[b * NPTS + i0 + tid], __float_as_uint(cand));
            if (!diag) {
                float mc = fminf(red_col[tid * 2 + 0], red_col[tid * 2 + 1]);
                float cc = fmaxf(qsg[j0 + tid] + mc, 0.0f);
                atomicMin(&g_minsq[b * NPTS + j0 + tid], __float_as_uint(cc));
            }
        }

        cb = nb; cit = nit; cjt = njt;
    }
}

// ---------------------------------------------------------------------------
// Kernel 3: sqrt + mean / std(ddof=1) / cv (double accum)
// ---------------------------------------------------------------------------
__global__ void finalize_kernel(float* __restrict__ out) {
    const int tid = threadIdx.x;
    double s0 = 0.0, q0 = 0.0, s1 = 0.0, q1 = 0.0;
    for (int i = tid; i < BATCH * NPTS; i += 2048) {
        double v0 = (double)sqrtf(__uint_as_float(g_minsq[i]));
        double v1 = (double)sqrtf(__uint_as_float(g_minsq[i + 1024]));
        s0 += v0; q0 += v0 * v0;
        s1 += v1; q1 += v1 * v1;
    }
    double s = s0 + s1, q = q0 + q1;
    #pragma unroll
    for (int o = 16; o; o >>= 1) {
        s += __shfl_xor_sync(0xffffffffu, s, o);
        q += __shfl_xor_sync(0xffffffffu, q, o);
    }
    __shared__ double ss[32], sq[32];
    int w = tid >> 5, l = tid & 31;
    if (l == 0) { ss[w] = s; sq[w] = q; }
    __syncthreads();
    if (w == 0) {
        s = ss[l];
        q = sq[l];
        #pragma unroll
        for (int o = 16; o; o >>= 1) {
            s += __shfl_xor_sync(0xffffffffu, s, o);
            q += __shfl_xor_sync(0xffffffffu, q, o);
        }
        if (l == 0) {
            const double n = (double)(BATCH * NPTS);
            double mean = s / n;
            double var  = (q - s * s / n) / (n - 1.0);
            double sd   = sqrt(var > 0.0 ? var : 0.0);
            double cv   = (mean > 1e-8) ? sd / mean : 0.0;
            out[0] = (float)mean;
            out[1] = (float)sd;
            out[2] = (float)cv;
        }
    }
}

// ---------------------------------------------------------------------------
extern "C" void kernel_launch(void* const* d_in, const int* in_sizes, int n_in,
                              void* d_out, int out_size) {
    const float* x = (const float*)d_in[0];
    float* out = (float*)d_out;

    cudaFuncSetAttribute(nnd_persist_kernel,
                         cudaFuncAttributeMaxDynamicSharedMemorySize, SMEM_TOTAL);

    prep_kernel<<<512, 256>>>(x);

    nnd_persist_kernel<<<NSM, 256, SMEM_TOTAL>>>();

    finalize_kernel<<<1, 1024>>>(out);
}

// round 11
// speedup vs baseline: 1.1330x; 1.1330x over previous
#include <cuda_runtime.h>
#include <cuda_bf16.h>
#include <math.h>
#include <cstdint>

#define BATCH 16
#define NPTS  2048
#define DIM   128
#define TILE  128
#define NJT   (NPTS / TILE)            // 16
#define NPAIRS (NJT * (NJT + 1) / 2)   // 136
#define NITEMS (NPAIRS * BATCH)        // 2176
#define NCTAS (152 * 2)                // 2 CTAs per SM -> true occ 2

// ---------------- scratch (no runtime allocation allowed) -------------------
__device__ float         g_sqnorms[BATCH * NPTS];
__device__ unsigned int  g_minsq[BATCH * NPTS];      // fp32 bits, atomicMin
__device__ __nv_bfloat16 g_hi[BATCH * NPTS * DIM];   // 8 MB

// ---------------- smem: A 32K | B0 32K | B1 32K | red 3K --------------------
#define SM_A     0u
#define SM_B(s)  (32768u + (uint32_t)(s) * 32768u)
#define SM_RED   98304
#define SMEM_TOTAL (98304 + 3072)

__device__ __forceinline__ uint32_t swz(uint32_t off) {
    return off ^ ((off >> 4) & 0x70);
}
__device__ __forceinline__ uint32_t smem_u32(const void* p) {
    uint32_t a;
    asm("{ .reg .u64 t; cvta.to.shared.u64 t, %1; cvt.u32.u64 %0, t; }"
        : "=r"(a) : "l"(p));
    return a;
}
__device__ __forceinline__ void cp16(uint32_t dst, const void* src) {
    asm volatile("cp.async.ca.shared.global [%0], [%1], 16;" :: "r"(dst), "l"(src));
}
#define CP_COMMIT() asm volatile("cp.async.commit_group;" ::: "memory")

__device__ __forceinline__ void ldsm_x4(unsigned* r, uint32_t addr) {
    asm volatile("ldmatrix.sync.aligned.m8n8.x4.shared.b16 {%0,%1,%2,%3}, [%4];"
        : "=r"(r[0]), "=r"(r[1]), "=r"(r[2]), "=r"(r[3]) : "r"(addr));
}
__device__ __forceinline__ void ldsm_x2(unsigned* r, uint32_t addr) {
    asm volatile("ldmatrix.sync.aligned.m8n8.x2.shared.b16 {%0,%1}, [%2];"
        : "=r"(r[0]), "=r"(r[1]) : "r"(addr));
}
__device__ __forceinline__ void mma16816(float* d, const unsigned* a, const unsigned* b) {
    asm volatile(
        "mma.sync.aligned.m16n8k16.row.col.f32.bf16.bf16.f32 "
        "{%0,%1,%2,%3}, {%4,%5,%6,%7}, {%8,%9}, {%0,%1,%2,%3};"
        : "+f"(d[0]), "+f"(d[1]), "+f"(d[2]), "+f"(d[3])
        : "r"(a[0]), "r"(a[1]), "r"(a[2]), "r"(a[3]), "r"(b[0]), "r"(b[1]));
}

__device__ __forceinline__ void decode_item(int item, int& b, int& it, int& jt) {
    b = item / NPAIRS;
    int rem = item - b * NPAIRS;
    int i = 0;
    while (rem >= NJT - i) { rem -= NJT - i; i++; }
    it = i; jt = i + rem;
}

// cp.async a 128x128 bf16 tile into swizzled 256B-row smem
__device__ __forceinline__ void cp_tile(uint32_t smem_u, uint32_t off,
                                        const __nv_bfloat16* g, int row0, int tid) {
    const uint4* src = (const uint4*)(g + (size_t)row0 * DIM);
    #pragma unroll
    for (int it = 0; it < 8; it++) {
        int idx = tid + 256 * it;
        cp16(smem_u + off + swz((uint32_t)idx * 16u), src + idx);
    }
}

// ---------------------------------------------------------------------------
// Kernel 1: per-row sqnorm + bf16 hi plane + minsq init (warp loops 8 rows)
// ---------------------------------------------------------------------------
__global__ void prep_kernel(const float* __restrict__ x) {
    int warp_id = (blockIdx.x * blockDim.x + threadIdx.x) >> 5;
    int lane    = threadIdx.x & 31;
    int row0    = warp_id * 8;
    if (row0 >= BATCH * NPTS) return;
    #pragma unroll
    for (int r = 0; r < 8; r++) {
        int row = row0 + r;
        float4 v = ((const float4*)(x + (size_t)row * DIM))[lane];
        float s = v.x * v.x + v.y * v.y + v.z * v.z + v.w * v.w;
        #pragma unroll
        for (int o = 16; o; o >>= 1) s += __shfl_xor_sync(0xffffffffu, s, o);

        __nv_bfloat162* ph = (__nv_bfloat162*)g_hi;
        int base = row * 64 + lane * 2;
        ph[base]     = __halves2bfloat162(__float2bfloat16(v.x), __float2bfloat16(v.y));
        ph[base + 1] = __halves2bfloat162(__float2bfloat16(v.z), __float2bfloat16(v.w));
        if (lane == 0) {
            g_sqnorms[row] = s;
            g_minsq[row]   = 0x7F800000u;   // +inf
        }
    }
}

// ---------------------------------------------------------------------------
// Kernel 2: persistent CTAs (2 per SM), contiguous item chunks. A-resident,
// B double-buffered one item ahead. Peer CTA covers waits/epilogues.
// Group discipline: wait_group 1 leaves exactly the newest B prefetch
// pending; A boundary loads are older groups and thus complete.
// ---------------------------------------------------------------------------
__global__ __launch_bounds__(256, 2)
void nnd_persist_kernel() {
    extern __shared__ char smem[];
    const int tid  = threadIdx.x;
    const int lane = tid & 31;
    const int wid  = tid >> 5;
    const int wm   = wid >> 2;
    const int wn   = wid & 3;
    const uint32_t smem_u = smem_u32(smem);

    const int r8  = lane & 7;
    const int q   = lane >> 3;
    const int l15 = lane & 15;
    const int rb  = l15 & 7;
    const int hb  = l15 >> 3;
    const int g   = lane >> 2;
    const int t   = lane & 3;

    float* red_row = (float*)(smem + SM_RED);          // [128][4]
    float* red_col = (float*)(smem + SM_RED + 2048);   // [128][2]

    const uint32_t a_row = (uint32_t)(wm * 64 + ((q & 1) << 3) + r8);
    const uint32_t a_kq  = (uint32_t)((q >> 1) << 4);
    const uint32_t b_row = (uint32_t)(wn * 32 + rb);
    const uint32_t b_kq  = (uint32_t)(hb << 4);

    // contiguous chunk [n0, n1)
    const int n0 = (int)((long long)blockIdx.x * NITEMS / NCTAS);
    const int n1 = (int)((long long)(blockIdx.x + 1) * NITEMS / NCTAS);
    const int len = n1 - n0;

    int cb, cit, cjt;                       // current item decode
    decode_item(n0, cb, cit, cjt);

    // prologue: A + B(stage0) for first item, one group
    {
        const __nv_bfloat16* Hb = g_hi + (size_t)cb * NPTS * DIM;
        cp_tile(smem_u, SM_A, Hb, cit * TILE, tid);
        if (cjt != cit) cp_tile(smem_u, SM_B(0), Hb, cjt * TILE, tid);
        CP_COMMIT();
    }

    int nb = cb, nit = cit, njt = cjt;      // next item decode (carried)

    for (int l = 0; l < len; l++) {
        const int s = l & 1;
        const int b = cb, it = cit, jt = cjt;
        const bool diag = (it == jt);

        // prefetch NEXT item's B into the other stage
        bool have_next = (l + 1 < len);
        bool a_changes = false;
        if (have_next) {
            decode_item(n0 + l + 1, nb, nit, njt);
            a_changes = (nb != b) || (nit != it);
            const __nv_bfloat16* Hn = g_hi + (size_t)nb * NPTS * DIM;
            if (njt != nit) cp_tile(smem_u, SM_B(s ^ 1), Hn, njt * TILE, tid);
        }
        CP_COMMIT();                        // always commit (possibly empty)

        asm volatile("cp.async.wait_group 1;" ::: "memory");
        __syncthreads();

        const int i0 = it * TILE, j0 = jt * TILE;
        const float* qsg = g_sqnorms + b * NPTS;
        const uint32_t sa = smem_u + SM_A;
        const uint32_t sb = diag ? sa : (smem_u + SM_B(s));

        float d[4][4][4];
        #pragma unroll
        for (int mt = 0; mt < 4; mt++)
            #pragma unroll
            for (int nt = 0; nt < 4; nt++)
                #pragma unroll
                for (int e = 0; e < 4; e++) d[mt][nt][e] = 0.0f;

        #pragma unroll
        for (int ks = 0; ks < 8; ks++) {
            const uint32_t kb = (uint32_t)ks * 32u;
            unsigned ah[4][4], bf[4][2];
            #pragma unroll
            for (int mt = 0; mt < 4; mt++)
                ldsm_x4(ah[mt], sa + swz((a_row + (uint32_t)(mt * 16)) * 256u + kb + a_kq));
            #pragma unroll
            for (int nt = 0; nt < 4; nt++)
                ldsm_x2(bf[nt], sb + swz((b_row + (uint32_t)(nt * 8)) * 256u + kb + b_kq));
            #pragma unroll
            for (int mt = 0; mt < 4; mt++)
                #pragma unroll
                for (int nt = 0; nt < 4; nt++)
                    mma16816(d[mt][nt], ah[mt], bf[nt]);
        }

        // ---- epilogue: row-side mins ----
        float rmin[8];
        #pragma unroll
        for (int r = 0; r < 8; r++) rmin[r] = 3.4e38f;
        #pragma unroll
        for (int nt = 0; nt < 4; nt++) {
            const int gc0 = j0 + wn * 32 + nt * 8 + 2 * t;
            const float qjx = qsg[gc0], qjy = qsg[gc0 + 1];
            #pragma unroll
            for (int mt = 0; mt < 4; mt++) {
                const int gr0 = i0 + wm * 64 + mt * 16 + g;
                const int gr1 = gr0 + 8;
                float c00 = fmaf(-2.0f, d[mt][nt][0], qjx);
                float c01 = fmaf(-2.0f, d[mt][nt][1], qjy);
                float c10 = fmaf(-2.0f, d[mt][nt][2], qjx);
                float c11 = fmaf(-2.0f, d[mt][nt][3], qjy);
                if (!diag || gr0 != gc0)     rmin[2*mt]   = fminf(rmin[2*mt],   c00);
                if (!diag || gr0 != gc0 + 1) rmin[2*mt]   = fminf(rmin[2*mt],   c01);
                if (!diag || gr1 != gc0)     rmin[2*mt+1] = fminf(rmin[2*mt+1], c10);
                if (!diag || gr1 != gc0 + 1) rmin[2*mt+1] = fminf(rmin[2*mt+1], c11);
            }
        }
        #pragma unroll
        for (int r = 0; r < 8; r++) {
            rmin[r] = fminf(rmin[r], __shfl_xor_sync(0xffffffffu, rmin[r], 1));
            rmin[r] = fminf(rmin[r], __shfl_xor_sync(0xffffffffu, rmin[r], 2));
        }
        __syncthreads();                    // all warps done with A smem

        // boundary: issue next A load now (overlaps epilogue below)
        if (have_next && a_changes) {
            cp_tile(smem_u, SM_A, g_hi + (size_t)nb * NPTS * DIM, nit * TILE, tid);
            CP_COMMIT();
        }

        if (t == 0) {
            #pragma unroll
            for (int mt = 0; mt < 4; mt++) {
                int rl = wm * 64 + mt * 16 + g;
                red_row[rl * 4 + wn]       = rmin[2 * mt];
                red_row[(rl + 8) * 4 + wn] = rmin[2 * mt + 1];
            }
        }

        // ---- col-side mins (off-diagonal tiles only) ----
        if (!diag) {
            float cmin[4][2];
            #pragma unroll
            for (int nt = 0; nt < 4; nt++) { cmin[nt][0] = 3.4e38f; cmin[nt][1] = 3.4e38f; }
            #pragma unroll
            for (int mt = 0; mt < 4; mt++) {
                const int gr0 = i0 + wm * 64 + mt * 16 + g;
                const float qi0 = qsg[gr0], qi1 = qsg[gr0 + 8];
                #pragma unroll
                for (int nt = 0; nt < 4; nt++) {
                    cmin[nt][0] = fminf(cmin[nt][0], fmaf(-2.0f, d[mt][nt][0], qi0));
                    cmin[nt][1] = fminf(cmin[nt][1], fmaf(-2.0f, d[mt][nt][1], qi0));
                    cmin[nt][0] = fminf(cmin[nt][0], fmaf(-2.0f, d[mt][nt][2], qi1));
                    cmin[nt][1] = fminf(cmin[nt][1], fmaf(-2.0f, d[mt][nt][3], qi1));
                }
            }
            #pragma unroll
            for (int nt = 0; nt < 4; nt++)
                #pragma unroll
                for (int e = 0; e < 2; e++) {
                    float v = cmin[nt][e];
                    v = fminf(v, __shfl_xor_sync(0xffffffffu, v, 4));
                    v = fminf(v, __shfl_xor_sync(0xffffffffu, v, 8));
                    v = fminf(v, __shfl_xor_sync(0xffffffffu, v, 16));
                    cmin[nt][e] = v;
                }
            if (lane < 4) {
                #pragma unroll
                for (int nt = 0; nt < 4; nt++) {
                    int c0 = wn * 32 + nt * 8 + 2 * lane;
                    red_col[c0 * 2 + wm]       = cmin[nt][0];
                    red_col[(c0 + 1) * 2 + wm] = cmin[nt][1];
                }
            }
        }
        __syncthreads();

        if (tid < 128) {
            float m = fminf(fminf(red_row[tid * 4 + 0], red_row[tid * 4 + 1]),
                            fminf(red_row[tid * 4 + 2], red_row[tid * 4 + 3]));
            float cand = fmaxf(qsg[i0 + tid] + m, 0.0f);
            atomicMin(&g_minsq[b * NPTS + i0 + tid], __float_as_uint(cand));
            if (!diag) {
                float mc = fminf(red_col[tid * 2 + 0], red_col[tid * 2 + 1]);
                float cc = fmaxf(qsg[j0 + tid] + mc, 0.0f);
                atomicMin(&g_minsq[b * NPTS + j0 + tid], __float_as_uint(cc));
            }
        }

        cb = nb; cit = nit; cjt = njt;
    }
}

// ---------------------------------------------------------------------------
// Kernel 3: sqrt + mean / std(ddof=1) / cv (double accum)
// ---------------------------------------------------------------------------
__global__ void finalize_kernel(float* __restrict__ out) {
    const int tid = threadIdx.x;
    double s0 = 0.0, q0 = 0.0, s1 = 0.0, q1 = 0.0;
    for (int i = tid; i < BATCH * NPTS; i += 2048) {
        double v0 = (double)sqrtf(__uint_as_float(g_minsq[i]));
        double v1 = (double)sqrtf(__uint_as_float(g_minsq[i + 1024]));
        s0 += v0; q0 += v0 * v0;
        s1 += v1; q1 += v1 * v1;
    }
    double s = s0 + s1, q = q0 + q1;
    #pragma unroll
    for (int o = 16; o; o >>= 1) {
        s += __shfl_xor_sync(0xffffffffu, s, o);
        q += __shfl_xor_sync(0xffffffffu, q, o);
    }
    __shared__ double ss[32], sq[32];
    int w = tid >> 5, l = tid & 31;
    if (l == 0) { ss[w] = s; sq[w] = q; }
    __syncthreads();
    if (w == 0) {
        s = ss[l];
        q = sq[l];
        #pragma unroll
        for (int o = 16; o; o >>= 1) {
            s += __shfl_xor_sync(0xffffffffu, s, o);
            q += __shfl_xor_sync(0xffffffffu, q, o);
        }
        if (l == 0) {
            const double n = (double)(BATCH * NPTS);
            double mean = s / n;
            double var  = (q - s * s / n) / (n - 1.0);
            double sd   = sqrt(var > 0.0 ? var : 0.0);
            double cv   = (mean > 1e-8) ? sd / mean : 0.0;
            out[0] = (float)mean;
            out[1] = (float)sd;
            out[2] = (float)cv;
        }
    }
}

// ---------------------------------------------------------------------------
extern "C" void kernel_launch(void* const* d_in, const int* in_sizes, int n_in,
                              void* d_out, int out_size) {
    const float* x = (const float*)d_in[0];
    float* out = (float*)d_out;

    cudaFuncSetAttribute(nnd_persist_kernel,
                         cudaFuncAttributeMaxDynamicSharedMemorySize, SMEM_TOTAL);

    prep_kernel<<<512, 256>>>(x);

    nnd_persist_kernel<<<NCTAS, 256, SMEM_TOTAL>>>();

    finalize_kernel<<<1, 1024>>>(out);
}